// round 10
// baseline (speedup 1.0000x reference)
#include <cuda_runtime.h>
#include <cuda_bf16.h>
#include <mma.h>
#include <cstdint>

using namespace nvcuda;
typedef __nv_bfloat16 bft;

constexpr int Bq = 16, Cc = 512, Nn = 4096;

// Scratch (device globals — no allocation allowed)
__device__ __align__(16) bft g_embh[2][Bq][Cc][Nn];   // bf16 rgb/geo
__device__ __align__(16) bft g_qkv[6][Bq][Cc][Nn];    // 0:Qp2r 1:Kp2r 2:Vp2r 3:Qr2p 4:Kr2p 5:Vr2p
__device__ __align__(16) bft g_wbf[8][Cc][Cc];        // 0..5 qkv weights, 6:proj_p2r 7:proj_r2p
__device__ __align__(16) bft g_outb[2][Bq][Cc][Nn];   // attention outputs per branch
__device__ __align__(16) float g_part[2][Bq][8][4][64][64];  // partial logits (4 N-splits)
__device__ __align__(16) bft g_probs[2][Bq][8][64][64];      // softmaxed probs

// ---------------------------------------------------------------------------
// cp.async helpers
// ---------------------------------------------------------------------------
__device__ __forceinline__ void cp16(void* s, const void* g) {
    unsigned ss = (unsigned)__cvta_generic_to_shared(s);
    asm volatile("cp.async.cg.shared.global [%0], [%1], 16;\n" ::"r"(ss), "l"(g));
}
__device__ __forceinline__ void cpcommit() { asm volatile("cp.async.commit_group;\n"); }
template <int W>
__device__ __forceinline__ void cpwait() { asm volatile("cp.async.wait_group %0;\n" ::"n"(W)); }

// ---------------------------------------------------------------------------
// K1a: convert embeddings fp32 -> bf16
// ---------------------------------------------------------------------------
__global__ void k_convert(const float* __restrict__ rgb, const float* __restrict__ geo) {
    size_t i = (size_t)(blockIdx.x * blockDim.x + threadIdx.x) * 4;
    float4 a = *reinterpret_cast<const float4*>(rgb + i);
    float4 b = *reinterpret_cast<const float4*>(geo + i);
    __nv_bfloat162* pr = reinterpret_cast<__nv_bfloat162*>(&g_embh[0][0][0][0] + i);
    __nv_bfloat162* pg = reinterpret_cast<__nv_bfloat162*>(&g_embh[1][0][0][0] + i);
    pr[0] = __floats2bfloat162_rn(a.x, a.y);
    pr[1] = __floats2bfloat162_rn(a.z, a.w);
    pg[0] = __floats2bfloat162_rn(b.x, b.y);
    pg[1] = __floats2bfloat162_rn(b.z, b.w);
}

// K1b: convert 8 weight matrices fp32 -> bf16
__global__ void k_convw(const float* w0, const float* w1, const float* w2, const float* w3,
                        const float* w4, const float* w5, const float* w6, const float* w7) {
    const float* ws[8] = {w0, w1, w2, w3, w4, w5, w6, w7};
    const int s = blockIdx.y;
    size_t i = (size_t)(blockIdx.x * blockDim.x + threadIdx.x) * 4;
    float4 a = *reinterpret_cast<const float4*>(ws[s] + i);
    __nv_bfloat162* p = reinterpret_cast<__nv_bfloat162*>(&g_wbf[s][0][0] + i);
    p[0] = __floats2bfloat162_rn(a.x, a.y);
    p[1] = __floats2bfloat162_rn(a.z, a.w);
}

// Dummy no-op kernel: positions k_gemm_qkv as the 4th launch for ncu capture.
__global__ void k_dummy() {}

// ---------------------------------------------------------------------------
// K2: QKV projections. C[512,4096] = W[512,512] @ X[512,4096].
// Tile 128(M) x 256(N), BK=64, 3-stage cp.async, single barrier per chunk.
// 8 warps as 2(M) x 4(N): warp tile 64x64 (acc 4x4 fp32).
// Register-level fragment double-buffering: prefetch kk+1 frags during kk MMAs.
// smem: As[3][128][72] @0 (55296) | Bs[3][64][264] @55296 (101376) = 156672
// grid=(16 n-tiles, 4 m-tiles, 96 = bb*6+combo), 256 thr
// ---------------------------------------------------------------------------
__global__ __launch_bounds__(256) void k_gemm_qkv() {
    extern __shared__ char sm[];
    bft (*As)[128][72] = reinterpret_cast<bft (*)[128][72]>(sm);
    bft (*Bs)[64][264] = reinterpret_cast<bft (*)[64][264]>(sm + 55296);

    const int z = blockIdx.z;
    const int bb = z / 6, combo = z % 6;
    const int geo_src = (combo >= 1 && combo <= 3) ? 1 : 0;
    const bft* __restrict__ Ag = &g_wbf[combo][0][0];
    const bft* __restrict__ Bg = &g_embh[geo_src][bb][0][0];
    bft* __restrict__ Cg = &g_qkv[combo][bb][0][0];
    const int m0 = blockIdx.y * 128, n0 = blockIdx.x * 256;
    const int tid = threadIdx.x, wid = tid >> 5, lane = tid & 31;
    const int wm = (wid & 1) * 64, wn = (wid >> 1) * 64;

    wmma::fragment<wmma::accumulator, 16, 16, 16, float> acc[4][4];
#pragma unroll
    for (int i = 0; i < 4; i++)
#pragma unroll
        for (int j = 0; j < 4; j++) wmma::fill_fragment(acc[i][j], 0.0f);

    auto pre = [&](int it, int buf) {
        const int k0 = it * 64;
#pragma unroll
        for (int p = 0; p < 4; p++) {
            int idx = tid + p * 256;
            int r = idx >> 3, c = (idx & 7) * 8;
            cp16(&As[buf][r][c], Ag + (m0 + r) * 512 + k0 + c);
        }
#pragma unroll
        for (int p = 0; p < 8; p++) {
            int idx = tid + p * 256;
            int r = idx >> 5, c = (idx & 31) * 8;
            cp16(&Bs[buf][r][c], Bg + (size_t)(k0 + r) * 4096 + n0 + c);
        }
        cpcommit();
    };

    pre(0, 0);
    pre(1, 1);
    for (int it = 0; it < 8; ++it) {
        const int buf = it % 3;
        if (it < 7) cpwait<1>();
        else        cpwait<0>();
        __syncthreads();
        if (it + 2 < 8) pre(it + 2, (it + 2) % 3);

        wmma::fragment<wmma::matrix_a, 16, 16, 16, bft, wmma::row_major> af[2][4];
        wmma::fragment<wmma::matrix_b, 16, 16, 16, bft, wmma::row_major> bfr[2][4];
        // load kk=0 fragments
#pragma unroll
        for (int i = 0; i < 4; i++)
            wmma::load_matrix_sync(af[0][i], &As[buf][wm + i * 16][0], 72);
#pragma unroll
        for (int j = 0; j < 4; j++)
            wmma::load_matrix_sync(bfr[0][j], &Bs[buf][0][wn + j * 16], 264);
#pragma unroll
        for (int kk = 0; kk < 4; kk++) {
            const int cur = kk & 1, nxt = cur ^ 1;
            if (kk < 3) {  // prefetch kk+1 fragments (overlaps with MMAs below)
#pragma unroll
                for (int i = 0; i < 4; i++)
                    wmma::load_matrix_sync(af[nxt][i], &As[buf][wm + i * 16][(kk + 1) * 16], 72);
#pragma unroll
                for (int j = 0; j < 4; j++)
                    wmma::load_matrix_sync(bfr[nxt][j], &Bs[buf][(kk + 1) * 16][wn + j * 16], 264);
            }
#pragma unroll
            for (int j = 0; j < 4; j++)
#pragma unroll
                for (int i = 0; i < 4; i++)
                    wmma::mma_sync(acc[i][j], af[cur][i], bfr[cur][j], acc[i][j]);
        }
    }
    __syncthreads();

    // Epilogue: per-warp 16x64 fp32 staging (aliases tile smem), fp32 -> bf16.
    float* Cw = reinterpret_cast<float*>(sm) + wid * 1024;
#pragma unroll
    for (int i = 0; i < 4; i++) {
#pragma unroll
        for (int j = 0; j < 4; j++)
            wmma::store_matrix_sync(Cw + j * 16, acc[i][j], 64, wmma::mem_row_major);
        __syncwarp();
        const int r = lane >> 1, c0 = (lane & 1) * 32;
        const float* src = Cw + r * 64 + c0;
        bft* dst = Cg + (size_t)(m0 + wm + i * 16 + r) * 4096 + n0 + wn + c0;
        uint4 o[4];
        __nv_bfloat162* ph = reinterpret_cast<__nv_bfloat162*>(o);
#pragma unroll
        for (int q = 0; q < 16; q++) ph[q] = __floats2bfloat162_rn(src[2 * q], src[2 * q + 1]);
#pragma unroll
        for (int q = 0; q < 4; q++) reinterpret_cast<uint4*>(dst)[q] = o[q];
        __syncwarp();
    }
}

// ---------------------------------------------------------------------------
// K4: fused output projections + residual:
//   out[b] = proj_p2r @ Out0 + proj_r2p @ Out1 + rgb + geo
// Same tiling as K2 (incl. register fragment double-buffering); 16 chunks.
// grid=(16,4,16), 256 thr, dyn smem 156672
// ---------------------------------------------------------------------------
__global__ __launch_bounds__(256) void k_gemm_final(const float* __restrict__ rgb,
                                                    const float* __restrict__ geo,
                                                    float* __restrict__ out) {
    extern __shared__ char sm[];
    bft (*As)[128][72] = reinterpret_cast<bft (*)[128][72]>(sm);
    bft (*Bs)[64][264] = reinterpret_cast<bft (*)[64][264]>(sm + 55296);

    const int bb = blockIdx.z;
    const int m0 = blockIdx.y * 128, n0 = blockIdx.x * 256;
    const int tid = threadIdx.x, wid = tid >> 5, lane = tid & 31;
    const int wm = (wid & 1) * 64, wn = (wid >> 1) * 64;

    wmma::fragment<wmma::accumulator, 16, 16, 16, float> acc[4][4];
#pragma unroll
    for (int i = 0; i < 4; i++)
#pragma unroll
        for (int j = 0; j < 4; j++) wmma::fill_fragment(acc[i][j], 0.0f);

    auto pre = [&](int ck, int buf) {
        const int brn = ck >> 3, k0 = (ck & 7) * 64;
        const bft* Ag = &g_wbf[6 + brn][0][0];
        const bft* Bg = &g_outb[brn][bb][0][0];
#pragma unroll
        for (int p = 0; p < 4; p++) {
            int idx = tid + p * 256;
            int r = idx >> 3, c = (idx & 7) * 8;
            cp16(&As[buf][r][c], Ag + (m0 + r) * 512 + k0 + c);
        }
#pragma unroll
        for (int p = 0; p < 8; p++) {
            int idx = tid + p * 256;
            int r = idx >> 5, c = (idx & 31) * 8;
            cp16(&Bs[buf][r][c], Bg + (size_t)(k0 + r) * 4096 + n0 + c);
        }
        cpcommit();
    };

    pre(0, 0);
    pre(1, 1);
    for (int it = 0; it < 16; ++it) {
        const int buf = it % 3;
        if (it < 15) cpwait<1>();
        else         cpwait<0>();
        __syncthreads();
        if (it + 2 < 16) pre(it + 2, (it + 2) % 3);

        wmma::fragment<wmma::matrix_a, 16, 16, 16, bft, wmma::row_major> af[2][4];
        wmma::fragment<wmma::matrix_b, 16, 16, 16, bft, wmma::row_major> bfr[2][4];
#pragma unroll
        for (int i = 0; i < 4; i++)
            wmma::load_matrix_sync(af[0][i], &As[buf][wm + i * 16][0], 72);
#pragma unroll
        for (int j = 0; j < 4; j++)
            wmma::load_matrix_sync(bfr[0][j], &Bs[buf][0][wn + j * 16], 264);
#pragma unroll
        for (int kk = 0; kk < 4; kk++) {
            const int cur = kk & 1, nxt = cur ^ 1;
            if (kk < 3) {
#pragma unroll
                for (int i = 0; i < 4; i++)
                    wmma::load_matrix_sync(af[nxt][i], &As[buf][wm + i * 16][(kk + 1) * 16], 72);
#pragma unroll
                for (int j = 0; j < 4; j++)
                    wmma::load_matrix_sync(bfr[nxt][j], &Bs[buf][(kk + 1) * 16][wn + j * 16], 264);
            }
#pragma unroll
            for (int j = 0; j < 4; j++)
#pragma unroll
                for (int i = 0; i < 4; i++)
                    wmma::mma_sync(acc[i][j], af[cur][i], bfr[cur][j], acc[i][j]);
        }
    }
    __syncthreads();

    // Epilogue: out = acc + rgb + geo (fp32)
    float* Cw = reinterpret_cast<float*>(sm) + wid * 1024;
    const size_t bplane = (size_t)bb * Cc * Nn;
#pragma unroll
    for (int i = 0; i < 4; i++) {
#pragma unroll
        for (int j = 0; j < 4; j++)
            wmma::store_matrix_sync(Cw + j * 16, acc[i][j], 64, wmma::mem_row_major);
        __syncwarp();
        const int r = lane >> 1, c0 = (lane & 1) * 32;
        const float* src = Cw + r * 64 + c0;
        const size_t off = bplane + (size_t)(m0 + wm + i * 16 + r) * 4096 + n0 + wn + c0;
#pragma unroll
        for (int q = 0; q < 8; q++) {
            float4 a = reinterpret_cast<const float4*>(src)[q];
            float4 rr = reinterpret_cast<const float4*>(rgb + off)[q];
            float4 gg = reinterpret_cast<const float4*>(geo + off)[q];
            a.x += rr.x + gg.x;
            a.y += rr.y + gg.y;
            a.z += rr.z + gg.z;
            a.w += rr.w + gg.w;
            reinterpret_cast<float4*>(out + off)[q] = a;
        }
        __syncwarp();
    }
}

// ---------------------------------------------------------------------------
// K3a: partial logits. L_part[64,64] = Q[64, ns-range] . K^T over 1024 cols.
// grid=(4 ns, 8 h, 32 = br*16+bb), 256 thr.
// dyn smem 102400: QS[2][64][136] @0, KS[2][64][136] @34816, Ls[2][64][64] @69632
// ---------------------------------------------------------------------------
__global__ __launch_bounds__(256) void k_attn1() {
    extern __shared__ char sm[];
    bft (*QS)[64][136] = reinterpret_cast<bft (*)[64][136]>(sm);
    bft (*KS)[64][136] = reinterpret_cast<bft (*)[64][136]>(sm + 34816);
    float (*Ls)[64][64] = reinterpret_cast<float (*)[64][64]>(sm + 69632);

    const int ns = blockIdx.x, h = blockIdx.y, z = blockIdx.z;
    const int br = z >> 4, bb = z & 15;
    const bft* __restrict__ Q  = &g_qkv[br * 3 + 0][bb][h * 64][0] + ns * 1024;
    const bft* __restrict__ Kk = &g_qkv[br * 3 + 1][bb][h * 64][0] + ns * 1024;
    const int tid = threadIdx.x, wid = tid >> 5;
    const int wm = (wid & 3) * 16, kh = wid >> 2;

    wmma::fragment<wmma::accumulator, 16, 16, 16, float> acc[4];
#pragma unroll
    for (int j = 0; j < 4; j++) wmma::fill_fragment(acc[j], 0.0f);

    auto pre = [&](int c, int buf) {
#pragma unroll
        for (int p = 0; p < 4; p++) {
            int idx = tid + p * 256;
            int r = idx >> 4, cl = (idx & 15) * 8;
            cp16(&QS[buf][r][cl], Q + (size_t)r * 4096 + c * 128 + cl);
            cp16(&KS[buf][r][cl], Kk + (size_t)r * 4096 + c * 128 + cl);
        }
        cpcommit();
    };
    pre(0, 0);
    for (int c = 0; c < 8; ++c) {
        const int buf = c & 1;
        cpwait<0>();
        __syncthreads();
        if (c < 7) pre(c + 1, buf ^ 1);
#pragma unroll
        for (int ks = 0; ks < 4; ks++) {
            wmma::fragment<wmma::matrix_a, 16, 16, 16, bft, wmma::row_major> af;
            wmma::load_matrix_sync(af, &QS[buf][wm][kh * 64 + ks * 16], 136);
#pragma unroll
            for (int j = 0; j < 4; j++) {
                wmma::fragment<wmma::matrix_b, 16, 16, 16, bft, wmma::col_major> bfr;
                wmma::load_matrix_sync(bfr, &KS[buf][j * 16][kh * 64 + ks * 16], 136);
                wmma::mma_sync(acc[j], af, bfr, acc[j]);
            }
        }
    }
#pragma unroll
    for (int j = 0; j < 4; j++)
        wmma::store_matrix_sync(&Ls[kh][wm][j * 16], acc[j], 64, wmma::mem_row_major);
    __syncthreads();

    // partial write: 256 threads x 16 floats
    {
        const int r = tid >> 2, c0 = (tid & 3) * 16;
        float* dst = &g_part[br][bb][h][ns][r][c0];
#pragma unroll
        for (int j = 0; j < 4; j++) {
            float4 a = *reinterpret_cast<const float4*>(&Ls[0][r][c0 + j * 4]);
            float4 b = *reinterpret_cast<const float4*>(&Ls[1][r][c0 + j * 4]);
            a.x += b.x; a.y += b.y; a.z += b.z; a.w += b.w;
            reinterpret_cast<float4*>(dst)[j] = a;
        }
    }
}

// ---------------------------------------------------------------------------
// K3b: reduce partials + softmax -> bf16 probs. grid=(8 h, 32 z), 64 thr.
// ---------------------------------------------------------------------------
__global__ __launch_bounds__(64) void k_softmax() {
    const int h = blockIdx.x, z = blockIdx.y;
    const int br = z >> 4, bb = z & 15;
    const int r = threadIdx.x;
    const float* p0 = &g_part[br][bb][h][0][r][0];
    float v[64];
#pragma unroll
    for (int j = 0; j < 16; j++) {
        float4 a = reinterpret_cast<const float4*>(p0)[j];
#pragma unroll
        for (int s = 1; s < 4; s++) {
            float4 b = reinterpret_cast<const float4*>(p0 + s * 4096)[j];
            a.x += b.x; a.y += b.y; a.z += b.z; a.w += b.w;
        }
        v[j * 4 + 0] = a.x; v[j * 4 + 1] = a.y; v[j * 4 + 2] = a.z; v[j * 4 + 3] = a.w;
    }
    const float scale = 0.125f;
    float mx = -1e30f;
#pragma unroll
    for (int j = 0; j < 64; j++) { v[j] *= scale; mx = fmaxf(mx, v[j]); }
    float s = 0.f;
#pragma unroll
    for (int j = 0; j < 64; j++) { v[j] = __expf(v[j] - mx); s += v[j]; }
    float inv = 1.0f / s;
    uint4 o[8];  // 64 bf16 = 128 bytes
    __nv_bfloat162* ph = reinterpret_cast<__nv_bfloat162*>(o);
#pragma unroll
    for (int j = 0; j < 32; j++) ph[j] = __floats2bfloat162_rn(v[2 * j] * inv, v[2 * j + 1] * inv);
    uint4* dst = reinterpret_cast<uint4*>(&g_probs[br][bb][h][r][0]);
#pragma unroll
    for (int j = 0; j < 8; j++) dst[j] = o[j];
}

// ---------------------------------------------------------------------------
// K3c: OutT[64, chunk] = probs^T @ V[64, chunk], chunk = 512 cols.
// grid=(8 nc, 8 h, 32 z), 256 thr.
// dyn smem 76800: VS[2][64][136] @0, Ps[64][72] @34816, OSw @44032 (32KB)
// ---------------------------------------------------------------------------
__global__ __launch_bounds__(256) void k_attn2() {
    extern __shared__ char sm[];
    bft (*VS)[64][136] = reinterpret_cast<bft (*)[64][136]>(sm);
    bft (*Ps)[72] = reinterpret_cast<bft (*)[72]>(sm + 34816);

    const int nc = blockIdx.x, h = blockIdx.y, z = blockIdx.z;
    const int br = z >> 4, bb = z & 15;
    const bft* __restrict__ V = &g_qkv[br * 3 + 2][bb][h * 64][0] + nc * 512;
    bft* __restrict__ O = &g_outb[br][bb][h * 64][0] + nc * 512;
    const bft* __restrict__ gp = &g_probs[br][bb][h][0][0];
    const int tid = threadIdx.x, wid = tid >> 5, lane = tid & 31;
    const int we = (wid & 3), wn = (wid >> 2) * 64;

    // load probs into padded smem
#pragma unroll
    for (int p = 0; p < 2; p++) {
        int idx = tid + p * 256;
        int r = idx >> 3, c = (idx & 7) * 8;
        *reinterpret_cast<uint4*>(&Ps[r][c]) =
            *reinterpret_cast<const uint4*>(gp + r * 64 + c);
    }

    auto pre = [&](int c, int buf) {
#pragma unroll
        for (int p = 0; p < 4; p++) {
            int idx = tid + p * 256;
            int r = idx >> 4, cl = (idx & 15) * 8;
            cp16(&VS[buf][r][cl], V + (size_t)r * 4096 + c * 128 + cl);
        }
        cpcommit();
    };
    pre(0, 0);
    __syncthreads();

    wmma::fragment<wmma::matrix_a, 16, 16, 16, bft, wmma::col_major> af[4];
#pragma unroll
    for (int d = 0; d < 4; d++)
        wmma::load_matrix_sync(af[d], &Ps[d * 16][we * 16], 72);

    float* OSw = reinterpret_cast<float*>(sm + 44032) + wid * 1024;  // 16x64 per warp
    for (int c = 0; c < 4; ++c) {
        const int buf = c & 1;
        cpwait<0>();
        __syncthreads();
        if (c < 3) pre(c + 1, buf ^ 1);
#pragma unroll
        for (int n4 = 0; n4 < 4; n4++) {
            wmma::fragment<wmma::accumulator, 16, 16, 16, float> oa;
            wmma::fill_fragment(oa, 0.0f);
#pragma unroll
            for (int d = 0; d < 4; d++) {
                wmma::fragment<wmma::matrix_b, 16, 16, 16, bft, wmma::row_major> bfr;
                wmma::load_matrix_sync(bfr, &VS[buf][d * 16][wn + n4 * 16], 136);
                wmma::mma_sync(oa, af[d], bfr, oa);
            }
            wmma::store_matrix_sync(OSw + n4 * 16, oa, 64, wmma::mem_row_major);
        }
        __syncwarp();
        {
            const int r = lane >> 1, c0 = (lane & 1) * 32;
            const float* src = OSw + r * 64 + c0;
            bft* dst = O + (size_t)(we * 16 + r) * 4096 + c * 128 + wn + c0;
            uint4 o[4];
            __nv_bfloat162* ph = reinterpret_cast<__nv_bfloat162*>(o);
#pragma unroll
            for (int q = 0; q < 16; q++)
                ph[q] = __floats2bfloat162_rn(src[2 * q], src[2 * q + 1]);
#pragma unroll
            for (int q = 0; q < 4; q++) reinterpret_cast<uint4*>(dst)[q] = o[q];
        }
        __syncwarp();
    }
}

// ---------------------------------------------------------------------------
// Launch. Input order: 0 rgb_emb, 1 geo_emb, 2 wq_rgb, 3 wk_rgb, 4 wv_rgb,
// 5 wq_point, 6 wk_point, 7 wv_point, 8 proj_r2p, 9 proj_p2r.
// ---------------------------------------------------------------------------
extern "C" void kernel_launch(void* const* d_in, const int* in_sizes, int n_in,
                              void* d_out, int out_size) {
    const float* rgb = (const float*)d_in[0];
    const float* geo = (const float*)d_in[1];

    cudaFuncSetAttribute(k_gemm_qkv, cudaFuncAttributeMaxDynamicSharedMemorySize, 156672);
    cudaFuncSetAttribute(k_gemm_final, cudaFuncAttributeMaxDynamicSharedMemorySize, 156672);
    cudaFuncSetAttribute(k_attn1, cudaFuncAttributeMaxDynamicSharedMemorySize, 102400);
    cudaFuncSetAttribute(k_attn2, cudaFuncAttributeMaxDynamicSharedMemorySize, 76800);

    k_convert<<<32768, 256>>>(rgb, geo);
    // weight slot order: 0 wq_rgb, 1 wk_point, 2 wv_point, 3 wq_point, 4 wk_rgb,
    //                    5 wv_rgb, 6 proj_p2r, 7 proj_r2p
    k_convw<<<dim3(256, 8), 256>>>((const float*)d_in[2], (const float*)d_in[6],
                                   (const float*)d_in[7], (const float*)d_in[5],
                                   (const float*)d_in[3], (const float*)d_in[4],
                                   (const float*)d_in[9], (const float*)d_in[8]);

    // dummy 3rd launch so the QKV GEMM is the 4th (profiled) launch
    k_dummy<<<1, 32>>>();

    // QKV projections: z = bb*6 + combo (batch-major for L2 reuse)
    k_gemm_qkv<<<dim3(16, 4, 96), 256, 156672>>>();

    // attention: partial logits -> softmax -> probs^T @ V
    k_attn1<<<dim3(4, 8, 32), 256, 102400>>>();
    k_softmax<<<dim3(8, 32), 64>>>();
    k_attn2<<<dim3(8, 8, 32), 256, 76800>>>();

    // fused output projections + residual -> d_out
    k_gemm_final<<<dim3(16, 4, 16), 256, 156672>>>(rgb, geo, (float*)d_out);
}

// round 11
// speedup vs baseline: 1.6958x; 1.6958x over previous
#include <cuda_runtime.h>
#include <cuda_bf16.h>
#include <mma.h>
#include <cstdint>

using namespace nvcuda;
typedef __nv_bfloat16 bft;

constexpr int Bq = 16, Cc = 512, Nn = 4096;

// Scratch (device globals — no allocation allowed)
__device__ __align__(16) bft   g_embh[2][Bq][Cc][Nn];   // bf16 X, [src][b][c][n], 0=rgb 1=geo
__device__ __align__(16) float g_gpart[4][Bq][Cc][Cc];  // gram split-k partials
__device__ __align__(16) float g_g[2][Bq][Cc][Cc];      // 0: G = Xr Xgᵀ, 1: Gᵀ
__device__ __align__(16) float g_y[2][Bq][Cc][Cc];      // Y = Wq · G_eff
__device__ __align__(16) float g_m[2][Bq][Cc][Cc];      // M = attn_blkᵀ · Wv
__device__ __align__(16) bft   g_t[2][Bq][Cc][Cc];      // T = proj · M (bf16)

// ---------------------------------------------------------------------------
// cp.async helpers
// ---------------------------------------------------------------------------
__device__ __forceinline__ void cp16(void* s, const void* g) {
    unsigned ss = (unsigned)__cvta_generic_to_shared(s);
    asm volatile("cp.async.cg.shared.global [%0], [%1], 16;\n" ::"r"(ss), "l"(g));
}
__device__ __forceinline__ void cpcommit() { asm volatile("cp.async.commit_group;\n"); }
template <int W>
__device__ __forceinline__ void cpwait() { asm volatile("cp.async.wait_group %0;\n" ::"n"(W)); }

// ---------------------------------------------------------------------------
// K1: convert embeddings fp32 -> bf16 (layout unchanged [b][c][n])
// ---------------------------------------------------------------------------
__global__ void k_convert(const float* __restrict__ rgb, const float* __restrict__ geo) {
    size_t i = (size_t)(blockIdx.x * blockDim.x + threadIdx.x) * 4;
    float4 a = *reinterpret_cast<const float4*>(rgb + i);
    float4 b = *reinterpret_cast<const float4*>(geo + i);
    __nv_bfloat162* pr = reinterpret_cast<__nv_bfloat162*>(&g_embh[0][0][0][0] + i);
    __nv_bfloat162* pg = reinterpret_cast<__nv_bfloat162*>(&g_embh[1][0][0][0] + i);
    pr[0] = __floats2bfloat162_rn(a.x, a.y);
    pr[1] = __floats2bfloat162_rn(a.z, a.w);
    pg[0] = __floats2bfloat162_rn(b.x, b.y);
    pg[1] = __floats2bfloat162_rn(b.z, b.w);
}

__global__ void k_dummy() {}

// ---------------------------------------------------------------------------
// K2: Gram partials. Gpart[s][b] = Xrgb[b][:, sN:(s+1)N] · Xgeo[b][:, ...]ᵀ
// NT bf16 gemm, tile 128x128, K=1024 per split, BK=64, 3-stage cp.async.
// 8 warps 2(M)x4(N), warp 64x32, acc 4x2.
// smem: As[3][128][72] (55296) | Bs[3][128][72] (55296) = 110592
// grid=(16 tiles, 4 splits, 16 b), 256 thr
// ---------------------------------------------------------------------------
__global__ __launch_bounds__(256) void k_gram() {
    extern __shared__ char sm[];
    bft (*As)[128][72] = reinterpret_cast<bft (*)[128][72]>(sm);
    bft (*Bs)[128][72] = reinterpret_cast<bft (*)[128][72]>(sm + 55296);

    const int it = blockIdx.x & 3, jt = blockIdx.x >> 2;
    const int s = blockIdx.y, b = blockIdx.z;
    const bft* __restrict__ A = &g_embh[0][b][it * 128][0] + s * 1024;
    const bft* __restrict__ B = &g_embh[1][b][jt * 128][0] + s * 1024;
    float* __restrict__ Cp = &g_gpart[s][b][it * 128][jt * 128];
    const int tid = threadIdx.x, wid = tid >> 5;
    const int wm = (wid & 1) * 64, wn = (wid >> 1) * 32;

    wmma::fragment<wmma::accumulator, 16, 16, 16, float> acc[4][2];
#pragma unroll
    for (int i = 0; i < 4; i++)
#pragma unroll
        for (int j = 0; j < 2; j++) wmma::fill_fragment(acc[i][j], 0.0f);

    auto pre = [&](int c, int buf) {
#pragma unroll
        for (int p = 0; p < 4; p++) {
            int idx = tid + p * 256;
            int r = idx >> 3, cl = (idx & 7) * 8;
            cp16(&As[buf][r][cl], A + (size_t)r * 4096 + c * 64 + cl);
            cp16(&Bs[buf][r][cl], B + (size_t)r * 4096 + c * 64 + cl);
        }
        cpcommit();
    };

    pre(0, 0);
    pre(1, 1);
    for (int c = 0; c < 16; ++c) {
        const int buf = c % 3;
        if (c < 15) cpwait<1>();
        else        cpwait<0>();
        __syncthreads();
        if (c + 2 < 16) pre(c + 2, (c + 2) % 3);
#pragma unroll
        for (int kk = 0; kk < 4; kk++) {
            wmma::fragment<wmma::matrix_a, 16, 16, 16, bft, wmma::row_major> af[4];
#pragma unroll
            for (int i = 0; i < 4; i++)
                wmma::load_matrix_sync(af[i], &As[buf][wm + i * 16][kk * 16], 72);
#pragma unroll
            for (int j = 0; j < 2; j++) {
                wmma::fragment<wmma::matrix_b, 16, 16, 16, bft, wmma::col_major> bfr;
                wmma::load_matrix_sync(bfr, &Bs[buf][wn + j * 16][kk * 16], 72);
#pragma unroll
                for (int i = 0; i < 4; i++)
                    wmma::mma_sync(acc[i][j], af[i], bfr, acc[i][j]);
            }
        }
    }
#pragma unroll
    for (int i = 0; i < 4; i++)
#pragma unroll
        for (int j = 0; j < 2; j++)
            wmma::store_matrix_sync(Cp + (wm + i * 16) * 512 + wn + j * 16, acc[i][j], 512,
                                    wmma::mem_row_major);
}

// ---------------------------------------------------------------------------
// K3: reduce gram partials -> G fp32 and Gᵀ fp32.
// grid = 16*512 CTAs of 128 thr, one (b, row i) per CTA, 4 floats per thread.
// ---------------------------------------------------------------------------
__global__ __launch_bounds__(128) void k_gred() {
    const int b = blockIdx.x >> 9, i = blockIdx.x & 511;
    const int j0 = threadIdx.x * 4;
    float4 v = *reinterpret_cast<const float4*>(&g_gpart[0][b][i][j0]);
#pragma unroll
    for (int s = 1; s < 4; s++) {
        float4 w = *reinterpret_cast<const float4*>(&g_gpart[s][b][i][j0]);
        v.x += w.x; v.y += w.y; v.z += w.z; v.w += w.w;
    }
    *reinterpret_cast<float4*>(&g_g[0][b][i][j0]) = v;
    g_g[1][b][j0 + 0][i] = v.x;
    g_g[1][b][j0 + 1][i] = v.y;
    g_g[1][b][j0 + 2][i] = v.z;
    g_g[1][b][j0 + 3][i] = v.w;
}

// ---------------------------------------------------------------------------
// K4: Y[br][b] = Wq_br · G_eff[b]   (tf32, 512x512x512)
// tile 128x128, BK=32, 3-stage, 8 warps 2x4 (warp 64x32, acc 4x2 m16n16k8).
// smem: As[3][128][36] f32 (55296) | Bs[3][32][132] f32 (50688) = 105984
// grid=(16 tiles, 1, 32 z), 256 thr
// ---------------------------------------------------------------------------
__global__ __launch_bounds__(256) void k_y(const float* __restrict__ wq0,
                                           const float* __restrict__ wq1) {
    extern __shared__ char sm[];
    float (*As)[128][36] = reinterpret_cast<float (*)[128][36]>(sm);
    float (*Bs)[32][132] = reinterpret_cast<float (*)[32][132]>(sm + 55296);

    const int it = blockIdx.x & 3, jt = blockIdx.x >> 2;
    const int z = blockIdx.z, br = z >> 4, b = z & 15;
    const float* __restrict__ A = br ? wq1 : wq0;
    const float* __restrict__ Bsrc = &g_g[br][b][0][0];
    float* __restrict__ C = &g_y[br][b][0][0];
    const int m0 = it * 128, n0 = jt * 128;
    const int tid = threadIdx.x, wid = tid >> 5;
    const int wm = (wid & 1) * 64, wn = (wid >> 1) * 32;

    wmma::fragment<wmma::accumulator, 16, 16, 8, float> acc[4][2];
#pragma unroll
    for (int i = 0; i < 4; i++)
#pragma unroll
        for (int j = 0; j < 2; j++) wmma::fill_fragment(acc[i][j], 0.0f);

    auto pre = [&](int ck, int buf) {
        const int k0 = ck * 32;
#pragma unroll
        for (int p = 0; p < 4; p++) {
            int idx = tid + p * 256;
            int r = idx >> 3, cl = (idx & 7) * 4;
            cp16(&As[buf][r][cl], A + (m0 + r) * 512 + k0 + cl);
            int r2 = idx >> 5, cl2 = (idx & 31) * 4;
            cp16(&Bs[buf][r2][cl2], Bsrc + (k0 + r2) * 512 + n0 + cl2);
        }
        cpcommit();
    };

    pre(0, 0);
    pre(1, 1);
    for (int c = 0; c < 16; ++c) {
        const int buf = c % 3;
        if (c < 15) cpwait<1>();
        else        cpwait<0>();
        __syncthreads();
        if (c + 2 < 16) pre(c + 2, (c + 2) % 3);
#pragma unroll
        for (int kk = 0; kk < 4; kk++) {
            wmma::fragment<wmma::matrix_a, 16, 16, 8, wmma::precision::tf32, wmma::row_major> af[4];
#pragma unroll
            for (int i = 0; i < 4; i++) {
                wmma::load_matrix_sync(af[i], &As[buf][wm + i * 16][kk * 8], 36);
#pragma unroll
                for (int t = 0; t < af[i].num_elements; t++)
                    af[i].x[t] = wmma::__float_to_tf32(af[i].x[t]);
            }
#pragma unroll
            for (int j = 0; j < 2; j++) {
                wmma::fragment<wmma::matrix_b, 16, 16, 8, wmma::precision::tf32, wmma::row_major> bfr;
                wmma::load_matrix_sync(bfr, &Bs[buf][kk * 8][wn + j * 16], 132);
#pragma unroll
                for (int t = 0; t < bfr.num_elements; t++)
                    bfr.x[t] = wmma::__float_to_tf32(bfr.x[t]);
#pragma unroll
                for (int i = 0; i < 4; i++)
                    wmma::mma_sync(acc[i][j], af[i], bfr, acc[i][j]);
            }
        }
    }
#pragma unroll
    for (int i = 0; i < 4; i++)
#pragma unroll
        for (int j = 0; j < 2; j++)
            wmma::store_matrix_sync(C + (m0 + wm + i * 16) * 512 + n0 + wn + j * 16, acc[i][j],
                                    512, wmma::mem_row_major);
}

// ---------------------------------------------------------------------------
// K5: per (head, z): logits_h = Y_h·Wk_hᵀ (tf32 NT, 64x64xK512); softmax;
//     M_h = attn_hᵀ·Wv_h (tf32 NN, 64x512xK64) -> g_m.
// smem 52224: Ys[64][68]@0, Wks[64][68]@17408, L[64][68]@34816; phase3 Wvs[64][132]@0
// grid=(8 h, 32 z), 256 thr
// ---------------------------------------------------------------------------
__global__ __launch_bounds__(256) void k_heads(const float* __restrict__ wk0,
                                               const float* __restrict__ wk1,
                                               const float* __restrict__ wv0,
                                               const float* __restrict__ wv1) {
    extern __shared__ char sm[];
    float (*Ys)[68]  = reinterpret_cast<float (*)[68]>(sm);
    float (*Wks)[68] = reinterpret_cast<float (*)[68]>(sm + 17408);
    float (*L)[68]   = reinterpret_cast<float (*)[68]>(sm + 34816);
    float (*Wvs)[132] = reinterpret_cast<float (*)[132]>(sm);  // phase-3 alias over Ys/Wks

    const int h = blockIdx.x, z = blockIdx.y, br = z >> 4, b = z & 15;
    const float* __restrict__ Y  = &g_y[br][b][h * 64][0];
    const float* __restrict__ Wk = (br ? wk1 : wk0) + h * 64 * 512;
    const float* __restrict__ Wv = (br ? wv1 : wv0) + h * 64 * 512;
    float* __restrict__ M = &g_m[br][b][h * 64][0];
    const int tid = threadIdx.x, wid = tid >> 5;

    // Phase 1: logits (64x64 over K=512), warps 4(M)x2(N)
    {
        const int wi = (wid & 3) * 16, wj = (wid >> 2) * 32;
        wmma::fragment<wmma::accumulator, 16, 16, 8, float> acc[2];
#pragma unroll
        for (int j = 0; j < 2; j++) wmma::fill_fragment(acc[j], 0.0f);

        for (int c = 0; c < 8; ++c) {
#pragma unroll
            for (int p = 0; p < 4; p++) {
                int idx = tid + p * 256;
                int r = idx >> 4, cl = (idx & 15) * 4;
                cp16(&Ys[r][cl], Y + r * 512 + c * 64 + cl);
                cp16(&Wks[r][cl], Wk + r * 512 + c * 64 + cl);
            }
            cpcommit();
            cpwait<0>();
            __syncthreads();
#pragma unroll
            for (int ks = 0; ks < 8; ks++) {
                wmma::fragment<wmma::matrix_a, 16, 16, 8, wmma::precision::tf32, wmma::row_major> af;
                wmma::load_matrix_sync(af, &Ys[wi][ks * 8], 68);
#pragma unroll
                for (int t = 0; t < af.num_elements; t++) af.x[t] = wmma::__float_to_tf32(af.x[t]);
#pragma unroll
                for (int j = 0; j < 2; j++) {
                    wmma::fragment<wmma::matrix_b, 16, 16, 8, wmma::precision::tf32, wmma::col_major> bfr;
                    wmma::load_matrix_sync(bfr, &Wks[wj + j * 16][ks * 8], 68);
#pragma unroll
                    for (int t = 0; t < bfr.num_elements; t++)
                        bfr.x[t] = wmma::__float_to_tf32(bfr.x[t]);
                    wmma::mma_sync(acc[j], af, bfr, acc[j]);
                }
            }
            __syncthreads();
        }
#pragma unroll
        for (int j = 0; j < 2; j++)
            wmma::store_matrix_sync(&L[wi][wj + j * 16], acc[j], 68, wmma::mem_row_major);
    }
    __syncthreads();

    // Phase 2: softmax rows (scale = d^-0.5 = 0.125), in place (fp32)
    if (tid < 64) {
        const float scale = 0.125f;
        float mx = -1e30f;
        for (int j = 0; j < 64; j++) mx = fmaxf(mx, L[tid][j] * scale);
        float s = 0.f;
        for (int j = 0; j < 64; j++) {
            float e = __expf(L[tid][j] * scale - mx);
            L[tid][j] = e;
            s += e;
        }
        float inv = 1.0f / s;
        for (int j = 0; j < 64; j++) L[tid][j] *= inv;
    }
    __syncthreads();

    // Phase 3: M_h[e][c] = sum_d attn[d][e] Wv_h[d][c], warps 4(e)x2(c-half)
    {
        const int we = (wid & 3) * 16, wc = (wid >> 2) * 64;
        for (int nc = 0; nc < 4; ++nc) {
#pragma unroll
            for (int p = 0; p < 8; p++) {
                int idx = tid + p * 256;
                int r = idx >> 5, cl = (idx & 31) * 4;
                cp16(&Wvs[r][cl], Wv + r * 512 + nc * 128 + cl);
            }
            cpcommit();
            cpwait<0>();
            __syncthreads();
            wmma::fragment<wmma::accumulator, 16, 16, 8, float> acc2[4];
#pragma unroll
            for (int j = 0; j < 4; j++) wmma::fill_fragment(acc2[j], 0.0f);
#pragma unroll
            for (int ks = 0; ks < 8; ks++) {
                // A[e][d] = attn[d][e] -> col_major over L
                wmma::fragment<wmma::matrix_a, 16, 16, 8, wmma::precision::tf32, wmma::col_major> af;
                wmma::load_matrix_sync(af, &L[ks * 8][we], 68);
#pragma unroll
                for (int t = 0; t < af.num_elements; t++) af.x[t] = wmma::__float_to_tf32(af.x[t]);
#pragma unroll
                for (int j = 0; j < 4; j++) {
                    wmma::fragment<wmma::matrix_b, 16, 16, 8, wmma::precision::tf32, wmma::row_major> bfr;
                    wmma::load_matrix_sync(bfr, &Wvs[ks * 8][wc + j * 16], 132);
#pragma unroll
                    for (int t = 0; t < bfr.num_elements; t++)
                        bfr.x[t] = wmma::__float_to_tf32(bfr.x[t]);
                    wmma::mma_sync(acc2[j], af, bfr, acc2[j]);
                }
            }
#pragma unroll
            for (int j = 0; j < 4; j++)
                wmma::store_matrix_sync(M + we * 512 + nc * 128 + wc + j * 16, acc2[j], 512,
                                        wmma::mem_row_major);
            __syncthreads();
        }
    }
}

// ---------------------------------------------------------------------------
// K6: T[br][b] = proj_br · M[br][b] (tf32, 512x512x512), output bf16.
// Same skeleton as k_y; epilogue stages through smem -> bf16.
// grid=(16, 1, 32), 256 thr, dyn smem 105984
// ---------------------------------------------------------------------------
__global__ __launch_bounds__(256) void k_T(const float* __restrict__ pj0,
                                           const float* __restrict__ pj1) {
    extern __shared__ char sm[];
    float (*As)[128][36] = reinterpret_cast<float (*)[128][36]>(sm);
    float (*Bs)[32][132] = reinterpret_cast<float (*)[32][132]>(sm + 55296);

    const int it = blockIdx.x & 3, jt = blockIdx.x >> 2;
    const int z = blockIdx.z, br = z >> 4, b = z & 15;
    const float* __restrict__ A = br ? pj1 : pj0;
    const float* __restrict__ Bsrc = &g_m[br][b][0][0];
    bft* __restrict__ C = &g_t[br][b][0][0];
    const int m0 = it * 128, n0 = jt * 128;
    const int tid = threadIdx.x, wid = tid >> 5, lane = tid & 31;
    const int wm = (wid & 1) * 64, wn = (wid >> 1) * 32;

    wmma::fragment<wmma::accumulator, 16, 16, 8, float> acc[4][2];
#pragma unroll
    for (int i = 0; i < 4; i++)
#pragma unroll
        for (int j = 0; j < 2; j++) wmma::fill_fragment(acc[i][j], 0.0f);

    auto pre = [&](int ck, int buf) {
        const int k0 = ck * 32;
#pragma unroll
        for (int p = 0; p < 4; p++) {
            int idx = tid + p * 256;
            int r = idx >> 3, cl = (idx & 7) * 4;
            cp16(&As[buf][r][cl], A + (m0 + r) * 512 + k0 + cl);
            int r2 = idx >> 5, cl2 = (idx & 31) * 4;
            cp16(&Bs[buf][r2][cl2], Bsrc + (k0 + r2) * 512 + n0 + cl2);
        }
        cpcommit();
    };

    pre(0, 0);
    pre(1, 1);
    for (int c = 0; c < 16; ++c) {
        const int buf = c % 3;
        if (c < 15) cpwait<1>();
        else        cpwait<0>();
        __syncthreads();
        if (c + 2 < 16) pre(c + 2, (c + 2) % 3);
#pragma unroll
        for (int kk = 0; kk < 4; kk++) {
            wmma::fragment<wmma::matrix_a, 16, 16, 8, wmma::precision::tf32, wmma::row_major> af[4];
#pragma unroll
            for (int i = 0; i < 4; i++) {
                wmma::load_matrix_sync(af[i], &As[buf][wm + i * 16][kk * 8], 36);
#pragma unroll
                for (int t = 0; t < af[i].num_elements; t++)
                    af[i].x[t] = wmma::__float_to_tf32(af[i].x[t]);
            }
#pragma unroll
            for (int j = 0; j < 2; j++) {
                wmma::fragment<wmma::matrix_b, 16, 16, 8, wmma::precision::tf32, wmma::row_major> bfr;
                wmma::load_matrix_sync(bfr, &Bs[buf][kk * 8][wn + j * 16], 132);
#pragma unroll
                for (int t = 0; t < bfr.num_elements; t++)
                    bfr.x[t] = wmma::__float_to_tf32(bfr.x[t]);
#pragma unroll
                for (int i = 0; i < 4; i++)
                    wmma::mma_sync(acc[i][j], af[i], bfr, acc[i][j]);
            }
        }
    }
    __syncthreads();

    // Epilogue: smem staging fp32 -> bf16 (per-warp 16x32 region)
    float* Cw = reinterpret_cast<float*>(sm) + wid * 512;
#pragma unroll
    for (int i = 0; i < 4; i++) {
        wmma::store_matrix_sync(Cw, acc[i][0], 32, wmma::mem_row_major);
        wmma::store_matrix_sync(Cw + 16, acc[i][1], 32, wmma::mem_row_major);
        __syncwarp();
        const int r = lane & 15, half = lane >> 4;
        const float* src = Cw + r * 32 + half * 16;
        bft* dst = C + (m0 + wm + i * 16 + r) * 512 + n0 + wn + half * 16;
        uint4 o[2];
        __nv_bfloat162* ph = reinterpret_cast<__nv_bfloat162*>(o);
#pragma unroll
        for (int q = 0; q < 8; q++) ph[q] = __floats2bfloat162_rn(src[2 * q], src[2 * q + 1]);
        reinterpret_cast<uint4*>(dst)[0] = o[0];
        reinterpret_cast<uint4*>(dst)[1] = o[1];
        __syncwarp();
    }
}

// ---------------------------------------------------------------------------
// K7: fused final: out[b] = rgb + geo + T_p2r[b]·geo + T_r2p[b]·rgb
// bf16 gemm, tile 128x256, 16 chunks (2 branches x 8 of K=64), 3-stage.
// 8 warps 2x4, warp 64x64, acc 4x4. grid=(16,4,16), 256 thr, smem 156672
// ---------------------------------------------------------------------------
__global__ __launch_bounds__(256) void k_gemm_final(const float* __restrict__ rgb,
                                                    const float* __restrict__ geo,
                                                    float* __restrict__ out) {
    extern __shared__ char sm[];
    bft (*As)[128][72] = reinterpret_cast<bft (*)[128][72]>(sm);
    bft (*Bs)[64][264] = reinterpret_cast<bft (*)[64][264]>(sm + 55296);

    const int bb = blockIdx.z;
    const int m0 = blockIdx.y * 128, n0 = blockIdx.x * 256;
    const int tid = threadIdx.x, wid = tid >> 5, lane = tid & 31;
    const int wm = (wid & 1) * 64, wn = (wid >> 1) * 64;

    wmma::fragment<wmma::accumulator, 16, 16, 16, float> acc[4][4];
#pragma unroll
    for (int i = 0; i < 4; i++)
#pragma unroll
        for (int j = 0; j < 4; j++) wmma::fill_fragment(acc[i][j], 0.0f);

    auto pre = [&](int ck, int buf) {
        const int brn = ck >> 3, k0 = (ck & 7) * 64;
        const bft* Ag = &g_t[brn][bb][0][0];
        const bft* Bg = &g_embh[brn ? 0 : 1][bb][0][0];  // br0: Tp·geo, br1: Tr·rgb
#pragma unroll
        for (int p = 0; p < 4; p++) {
            int idx = tid + p * 256;
            int r = idx >> 3, c = (idx & 7) * 8;
            cp16(&As[buf][r][c], Ag + (m0 + r) * 512 + k0 + c);
        }
#pragma unroll
        for (int p = 0; p < 8; p++) {
            int idx = tid + p * 256;
            int r = idx >> 5, c = (idx & 31) * 8;
            cp16(&Bs[buf][r][c], Bg + (size_t)(k0 + r) * 4096 + n0 + c);
        }
        cpcommit();
    };

    pre(0, 0);
    pre(1, 1);
    for (int it = 0; it < 16; ++it) {
        const int buf = it % 3;
        if (it < 15) cpwait<1>();
        else         cpwait<0>();
        __syncthreads();
        if (it + 2 < 16) pre(it + 2, (it + 2) % 3);
#pragma unroll
        for (int kk = 0; kk < 64; kk += 16) {
            wmma::fragment<wmma::matrix_a, 16, 16, 16, bft, wmma::row_major> af[4];
#pragma unroll
            for (int i = 0; i < 4; i++)
                wmma::load_matrix_sync(af[i], &As[buf][wm + i * 16][kk], 72);
#pragma unroll
            for (int j = 0; j < 4; j++) {
                wmma::fragment<wmma::matrix_b, 16, 16, 16, bft, wmma::row_major> bfr;
                wmma::load_matrix_sync(bfr, &Bs[buf][kk][wn + j * 16], 264);
#pragma unroll
                for (int i = 0; i < 4; i++)
                    wmma::mma_sync(acc[i][j], af[i], bfr, acc[i][j]);
            }
        }
    }
    __syncthreads();

    // Epilogue: out = acc + rgb + geo (fp32)
    float* Cw = reinterpret_cast<float*>(sm) + wid * 1024;
    const size_t bplane = (size_t)bb * Cc * Nn;
#pragma unroll
    for (int i = 0; i < 4; i++) {
#pragma unroll
        for (int j = 0; j < 4; j++)
            wmma::store_matrix_sync(Cw + j * 16, acc[i][j], 64, wmma::mem_row_major);
        __syncwarp();
        const int r = lane >> 1, c0 = (lane & 1) * 32;
        const float* src = Cw + r * 64 + c0;
        const size_t off = bplane + (size_t)(m0 + wm + i * 16 + r) * 4096 + n0 + wn + c0;
#pragma unroll
        for (int q = 0; q < 8; q++) {
            float4 a = reinterpret_cast<const float4*>(src)[q];
            float4 rr = reinterpret_cast<const float4*>(rgb + off)[q];
            float4 gg = reinterpret_cast<const float4*>(geo + off)[q];
            a.x += rr.x + gg.x;
            a.y += rr.y + gg.y;
            a.z += rr.z + gg.z;
            a.w += rr.w + gg.w;
            reinterpret_cast<float4*>(out + off)[q] = a;
        }
        __syncwarp();
    }
}

// ---------------------------------------------------------------------------
// Launch. Input order: 0 rgb_emb, 1 geo_emb, 2 wq_rgb, 3 wk_rgb, 4 wv_rgb,
// 5 wq_point, 6 wk_point, 7 wv_point, 8 proj_r2p, 9 proj_p2r.
// Branch 0 (p2r): wq_rgb, wk_point, wv_point, proj_p2r, G,  X=geo
// Branch 1 (r2p): wq_point, wk_rgb,  wv_rgb,  proj_r2p, Gᵀ, X=rgb
// ---------------------------------------------------------------------------
extern "C" void kernel_launch(void* const* d_in, const int* in_sizes, int n_in,
                              void* d_out, int out_size) {
    const float* rgb = (const float*)d_in[0];
    const float* geo = (const float*)d_in[1];

    cudaFuncSetAttribute(k_gram, cudaFuncAttributeMaxDynamicSharedMemorySize, 110592);
    cudaFuncSetAttribute(k_y, cudaFuncAttributeMaxDynamicSharedMemorySize, 105984);
    cudaFuncSetAttribute(k_T, cudaFuncAttributeMaxDynamicSharedMemorySize, 105984);
    cudaFuncSetAttribute(k_heads, cudaFuncAttributeMaxDynamicSharedMemorySize, 52224);
    cudaFuncSetAttribute(k_gemm_final, cudaFuncAttributeMaxDynamicSharedMemorySize, 156672);

    k_convert<<<32768, 256>>>(rgb, geo);
    k_dummy<<<1, 32>>>();
    k_dummy<<<1, 32>>>();

    // Gram: G = Xrgb · Xgeoᵀ (split-k 4) — 4th launch (profiled)
    k_gram<<<dim3(16, 4, 16), 256, 110592>>>();
    k_gred<<<16 * 512, 128>>>();

    // Y = Wq · G_eff
    k_y<<<dim3(16, 1, 32), 256, 105984>>>((const float*)d_in[2], (const float*)d_in[5]);

    // per-head logits + softmax + M = attnᵀ·Wv
    k_heads<<<dim3(8, 32), 256, 52224>>>((const float*)d_in[6], (const float*)d_in[3],
                                         (const float*)d_in[7], (const float*)d_in[4]);

    // T = proj · M
    k_T<<<dim3(16, 1, 32), 256, 105984>>>((const float*)d_in[9], (const float*)d_in[8]);

    // out = rgb + geo + Tp·geo + Tr·rgb
    k_gemm_final<<<dim3(16, 4, 16), 256, 156672>>>(rgb, geo, (float*)d_out);
}